// round 12
// baseline (speedup 1.0000x reference)
#include <cuda_runtime.h>
#include <cstdint>

#define HDIM 128
#define TSEQ 512
#define BATCH 128
#define GB 4
#define RSTRIDE 132
#define WSTRIDE 132
#define ASTRIDE 132     // activation row stride; dims 64..127 live at float-offset 68
#define GSTRIDE 9       // gate-buffer row stride -> conflict-free scalar access

typedef unsigned long long u64;

__device__ float g_h2[(size_t)TSEQ * BATCH * HDIM];   // [t][b][h]
__device__ float g_dold[TSEQ * BATCH];
__device__ float g_dh[TSEQ * BATCH];

__device__ __forceinline__ float sigm(float x) {
    return __fdividef(1.f, 1.f + __expf(-x));
}
__device__ __forceinline__ float tanh_fast(float x) {
    x = fminf(fmaxf(x, -15.f), 15.f);
    float e = __expf(2.f * x);
    return __fdividef(e - 1.f, e + 1.f);
}
__device__ __forceinline__ u64 ffma2(u64 a, u64 b, u64 c) {
    u64 d;
    asm("fma.rn.f32x2 %0, %1, %2, %3;" : "=l"(d) : "l"(a), "l"(b), "l"(c));
    return d;
}
__device__ __forceinline__ float sum2(u64 v) {
    float lo, hi;
    asm("mov.b64 {%0, %1}, %2;" : "=f"(lo), "=f"(hi) : "l"(v));
    return lo + hi;
}
__device__ __forceinline__ u64 pack2(float a, float b) {
    u64 r;
    asm("mov.b64 %0, {%1, %2};" : "=l"(r) : "f"(a), "f"(b));
    return r;
}
__device__ __forceinline__ float2 unpk(u64 v) {
    float2 r;
    asm("mov.b64 {%0, %1}, %2;" : "=f"(r.x), "=f"(r.y) : "l"(v));
    return r;
}
__device__ __forceinline__ void st_cluster_f32(float* p, int rank, float v) {
    uint32_t la = (uint32_t)__cvta_generic_to_shared(p);
    uint32_t ra;
    asm volatile("mapa.shared::cluster.u32 %0, %1, %2;" : "=r"(ra) : "r"(la), "r"(rank));
    asm volatile("st.shared::cluster.f32 [%0], %1;" :: "r"(ra), "f"(v) : "memory");
}
__device__ __forceinline__ void mbar_init(uint32_t a, uint32_t cnt) {
    asm volatile("mbarrier.init.shared.b64 [%0], %1;" :: "r"(a), "r"(cnt) : "memory");
}
__device__ __forceinline__ void mbar_arrive_rank(uint32_t local_addr, uint32_t rank) {
    asm volatile(
        "{\n\t.reg .b32 ra;\n\t"
        "mapa.shared::cluster.u32 ra, %0, %1;\n\t"
        "mbarrier.arrive.release.cluster.shared::cluster.b64 _, [ra];\n\t}"
        :: "r"(local_addr), "r"(rank) : "memory");
}
__device__ __forceinline__ void mbar_wait(uint32_t addr, uint32_t parity) {
    asm volatile(
        "{\n\t.reg .pred P;\n"
        "WL_%=:\n\t"
        "mbarrier.try_wait.parity.acquire.cluster.shared::cta.b64 P, [%0], %1, 0x989680;\n\t"
        "@P bra WD_%=;\n\t"
        "bra WL_%=;\n"
        "WD_%=:\n\t}"
        :: "r"(addr), "r"(parity) : "memory");
}
__device__ __forceinline__ void cluster_sync_() {
    asm volatile("barrier.cluster.arrive.aligned;" ::: "memory");
    asm volatile("barrier.cluster.wait.aligned;" ::: "memory");
}

// ---------------------------------------------------------------------------
// Phase 1: 32 clusters x 4 CTAs, 4 batches/cluster, 256 threads/CTA.
// LAYER-SPLIT warp specialization (no CTA-wide sync in the loop):
//  Group A (tid<128):  layer 1. Whh1 row in REGISTERS (64 u64). Per iter:
//     [wait mb1(i-1)] -> mv1 -> bar1 -> [wait mb2(i-1): WAR cover for B's
//     c1 reads] -> cell1 (step i) + DSMEM h1/c1 -> bar1 -> elect arrive mb1.
//  Group B (tid>=128): layer 2. Wih2/Whh2 in SMEM (kh-gap layout). Thread
//     (u=lt>>1, kh=lt&1) covers gate rows 2u,2u+1 of BOTH matrices, kh half;
//     shfl_xor(1) combines halves. Per iter i (1..512):
//     wait mb1(i-1) [c1 data] + mb2(i-1) [h2 data + WAR] -> mv2 -> bar2 ->
//     cell2 (step i-1) + DSMEM h2 + g_h2 -> bar2 -> elect arrive mb2.
// Weight bytes/step unchanged vs R11 (W1 now 0 crossbar, W2 read once).
// Each SMSP holds one A-warp + one B-warp: stalls of one pipeline are
// covered by the other's math.
// ---------------------------------------------------------------------------
__global__ void __launch_bounds__(256, 1) __cluster_dims__(4, 1, 1)
lstm_seq_kernel(const float* __restrict__ x,
                const float* __restrict__ Wih1, const float* __restrict__ Whh1,
                const float* __restrict__ bih1, const float* __restrict__ bhh1,
                const float* __restrict__ Wih2, const float* __restrict__ Whh2,
                const float* __restrict__ bih2, const float* __restrict__ bhh2)
{
    extern __shared__ float sW2[];   // [256][WSTRIDE] rows 0-127 Wih2, 128-255 Whh2; kh-gap cols

    __shared__ __align__(16) float h1bc[2][GB * ASTRIDE];
    __shared__ __align__(16) float c1bc[2][GB * ASTRIDE];
    __shared__ __align__(16) float h2bc[2][GB * ASTRIDE];
    __shared__ float g1buf[128 * GSTRIDE];
    __shared__ float g2buf[128 * GSTRIDE];
    __shared__ float bias1s[128], bias2s[128], wih1s[128];
    __shared__ __align__(8) u64 mbar[2];

    const int tid  = threadIdx.x;
    const int rank = blockIdx.x & 3;
    const int bg0  = (blockIdx.x >> 2) * GB;
    const int lt   = tid & 127;

    const int cu   = lt & 31, cb = lt >> 5;
    const int slot = rank * 32 + cu;
    const int pos  = slot + (slot >= 64 ? 4 : 0);   // gap-layout position

    // ---- group A: Whh1 row lt -> registers (64 u64)
    u64 w1[64];
    if (tid < 128) {
        const int gr = (lt >> 5) * 128 + rank * 32 + (lt & 31);
        const float* src = Whh1 + (size_t)gr * 128;
        #pragma unroll
        for (int k = 0; k < 32; k++) {
            ulonglong2 v = ((const ulonglong2*)src)[k];
            w1[2 * k] = v.x; w1[2 * k + 1] = v.y;
        }
    }

    // ---- sW2: both layer-2 matrices, kh-gap column layout
    for (int idx = tid; idx < 256 * 32; idx += 256) {
        int j = idx >> 5, k4 = idx & 31;
        int jr = j & 127;
        int gr = (jr >> 5) * 128 + rank * 32 + (jr & 31);
        const float* src = ((j >> 7) ? Whh2 : Wih2) + (size_t)gr * 128 + k4 * 4;
        int dstc = (k4 < 16) ? (k4 * 4) : (k4 * 4 + 4);
        *(float4*)(sW2 + j * WSTRIDE + dstc) = *(const float4*)src;
    }
    if (tid < 128) {
        int gr = (tid >> 5) * 128 + rank * 32 + (tid & 31);
        bias1s[tid] = bih1[gr] + bhh1[gr];
        bias2s[tid] = bih2[gr] + bhh2[gr];
        wih1s[tid]  = Wih1[gr];
    }
    for (int idx = tid; idx < 2 * GB * ASTRIDE; idx += 256) {
        ((float*)h1bc)[idx] = 0.f;
        ((float*)c1bc)[idx] = 0.f;
        ((float*)h2bc)[idx] = 0.f;
    }
    const uint32_t mb1a = (uint32_t)__cvta_generic_to_shared(&mbar[0]);
    const uint32_t mb2a = (uint32_t)__cvta_generic_to_shared(&mbar[1]);
    if (tid == 0) { mbar_init(mb1a, 4); mbar_init(mb2a, 4); }
    __syncthreads();
    cluster_sync_();   // peers see zeroed buffers + initialized mbarriers

    if (tid < 128) {
        // ============================ GROUP A ============================
        float c1s = 0.f;
        const float* xp = x + (size_t)(bg0 + cb) * TSEQ;
        for (int i = 0; i < TSEQ; i++) {
            const int p  = i & 1;
            const int pn = p ^ 1;
            if (i > 0) mbar_wait(mb1a, (uint32_t)((i - 1) & 1));

            // mv1: reg row (full K) . h1(i-1), 4 batches (gap act layout)
            {
                const ulonglong2* hA = (const ulonglong2*)(&h1bc[p][0 * ASTRIDE]);
                const ulonglong2* hB = (const ulonglong2*)(&h1bc[p][1 * ASTRIDE]);
                const ulonglong2* hC = (const ulonglong2*)(&h1bc[p][2 * ASTRIDE]);
                const ulonglong2* hD = (const ulonglong2*)(&h1bc[p][3 * ASTRIDE]);
                u64 a0 = 0, a1 = 0, a2 = 0, a3 = 0;
                #pragma unroll
                for (int k = 0; k < 32; k++) {
                    int ki = k + (k >= 16 ? 1 : 0);   // skip gap at float 64..67
                    ulonglong2 v0 = hA[ki], v1 = hB[ki], v2 = hC[ki], v3 = hD[ki];
                    u64 wa = w1[2 * k], wb = w1[2 * k + 1];
                    a0 = ffma2(wa, v0.x, a0); a0 = ffma2(wb, v0.y, a0);
                    a1 = ffma2(wa, v1.x, a1); a1 = ffma2(wb, v1.y, a1);
                    a2 = ffma2(wa, v2.x, a2); a2 = ffma2(wb, v2.y, a2);
                    a3 = ffma2(wa, v3.x, a3); a3 = ffma2(wb, v3.y, a3);
                }
                g1buf[lt * GSTRIDE + 0] = sum2(a0);
                g1buf[lt * GSTRIDE + 1] = sum2(a1);
                g1buf[lt * GSTRIDE + 2] = sum2(a2);
                g1buf[lt * GSTRIDE + 3] = sum2(a3);
            }
            asm volatile("bar.sync 1, 128;" ::: "memory");
            if (i > 0) mbar_wait(mb2a, (uint32_t)((i - 1) & 1));  // B's reads of buf pn done

            // cell1 (step i)
            {
                float xv = __ldg(xp + i);
                float gi = g1buf[(cu)      * GSTRIDE + cb] + fmaf(wih1s[cu],      xv, bias1s[cu]);
                float gf = g1buf[(32 + cu) * GSTRIDE + cb] + fmaf(wih1s[32 + cu], xv, bias1s[32 + cu]);
                float gg = g1buf[(64 + cu) * GSTRIDE + cb] + fmaf(wih1s[64 + cu], xv, bias1s[64 + cu]);
                float go = g1buf[(96 + cu) * GSTRIDE + cb] + fmaf(wih1s[96 + cu], xv, bias1s[96 + cu]);
                c1s = sigm(gf) * c1s + sigm(gi) * tanh_fast(gg);
                float h1n = sigm(go) * tanh_fast(c1s);
                #pragma unroll
                for (int r = 0; r < 4; r++) {
                    st_cluster_f32(&h1bc[pn][cb * ASTRIDE + pos], r, h1n);
                    st_cluster_f32(&c1bc[pn][cb * ASTRIDE + pos], r, c1s);
                }
            }
            asm volatile("bar.sync 1, 128;" ::: "memory");
            if (lt == 0) {
                #pragma unroll
                for (int r = 0; r < 4; r++) mbar_arrive_rank(mb1a, r);
            }
        }
    } else {
        // ============================ GROUP B ============================
        const int u  = lt >> 1;
        const int kh = lt & 1;
        const int r0 = 2 * u, r1 = 2 * u + 1;
        float c2s = 0.f;
        float* gh2p = g_h2 + (size_t)(bg0 + cb) * HDIM + slot;

        if (lt == 0) {   // iteration-0 arrive so A's first mb2 wait passes
            #pragma unroll
            for (int r = 0; r < 4; r++) mbar_arrive_rank(mb2a, r);
        }
        for (int i = 1; i <= TSEQ; i++) {
            const int p  = i & 1;
            const int pn = p ^ 1;
            const uint32_t wpar = (uint32_t)((i - 1) & 1);
            mbar_wait(mb1a, wpar);   // c1(i-1) data
            mbar_wait(mb2a, wpar);   // h2(i-2) data + own WAR

            // mv2: gates2(step i-1) rows r0,r1 = Wih2.c1(i-1) + Whh2.h2(i-2), kh half
            {
                const ulonglong2* wi0 = (const ulonglong2*)(sW2 + r0 * WSTRIDE + kh * 68);
                const ulonglong2* wi1 = (const ulonglong2*)(sW2 + r1 * WSTRIDE + kh * 68);
                const ulonglong2* wh0 = (const ulonglong2*)(sW2 + (128 + r0) * WSTRIDE + kh * 68);
                const ulonglong2* wh1 = (const ulonglong2*)(sW2 + (128 + r1) * WSTRIDE + kh * 68);
                const ulonglong2* cA = (const ulonglong2*)(&c1bc[p][0 * ASTRIDE + kh * 68]);
                const ulonglong2* cB = (const ulonglong2*)(&c1bc[p][1 * ASTRIDE + kh * 68]);
                const ulonglong2* cC = (const ulonglong2*)(&c1bc[p][2 * ASTRIDE + kh * 68]);
                const ulonglong2* cD = (const ulonglong2*)(&c1bc[p][3 * ASTRIDE + kh * 68]);
                const ulonglong2* hA = (const ulonglong2*)(&h2bc[p][0 * ASTRIDE + kh * 68]);
                const ulonglong2* hB = (const ulonglong2*)(&h2bc[p][1 * ASTRIDE + kh * 68]);
                const ulonglong2* hC = (const ulonglong2*)(&h2bc[p][2 * ASTRIDE + kh * 68]);
                const ulonglong2* hD = (const ulonglong2*)(&h2bc[p][3 * ASTRIDE + kh * 68]);
                u64 p00 = 0, p01 = 0, p02 = 0, p03 = 0;
                u64 p10 = 0, p11 = 0, p12 = 0, p13 = 0;
                #pragma unroll
                for (int k = 0; k < 16; k++) {
                    ulonglong2 wiA = wi0[k], wiB = wi1[k];
                    ulonglong2 whA = wh0[k], whB = wh1[k];
                    ulonglong2 v0 = cA[k], v1 = cB[k], v2 = cC[k], v3 = cD[k];
                    ulonglong2 u0 = hA[k], u1 = hB[k], u2 = hC[k], u3 = hD[k];
                    p00 = ffma2(wiA.x, v0.x, p00); p00 = ffma2(wiA.y, v0.y, p00);
                    p00 = ffma2(whA.x, u0.x, p00); p00 = ffma2(whA.y, u0.y, p00);
                    p01 = ffma2(wiA.x, v1.x, p01); p01 = ffma2(wiA.y, v1.y, p01);
                    p01 = ffma2(whA.x, u1.x, p01); p01 = ffma2(whA.y, u1.y, p01);
                    p02 = ffma2(wiA.x, v2.x, p02); p02 = ffma2(wiA.y, v2.y, p02);
                    p02 = ffma2(whA.x, u2.x, p02); p02 = ffma2(whA.y, u2.y, p02);
                    p03 = ffma2(wiA.x, v3.x, p03); p03 = ffma2(wiA.y, v3.y, p03);
                    p03 = ffma2(whA.x, u3.x, p03); p03 = ffma2(whA.y, u3.y, p03);
                    p10 = ffma2(wiB.x, v0.x, p10); p10 = ffma2(wiB.y, v0.y, p10);
                    p10 = ffma2(whB.x, u0.x, p10); p10 = ffma2(whB.y, u0.y, p10);
                    p11 = ffma2(wiB.x, v1.x, p11); p11 = ffma2(wiB.y, v1.y, p11);
                    p11 = ffma2(whB.x, u1.x, p11); p11 = ffma2(whB.y, u1.y, p11);
                    p12 = ffma2(wiB.x, v2.x, p12); p12 = ffma2(wiB.y, v2.y, p12);
                    p12 = ffma2(whB.x, u2.x, p12); p12 = ffma2(whB.y, u2.y, p12);
                    p13 = ffma2(wiB.x, v3.x, p13); p13 = ffma2(wiB.y, v3.y, p13);
                    p13 = ffma2(whB.x, u3.x, p13); p13 = ffma2(whB.y, u3.y, p13);
                }
                float s00 = sum2(p00), s01 = sum2(p01), s02 = sum2(p02), s03 = sum2(p03);
                float s10 = sum2(p10), s11 = sum2(p11), s12 = sum2(p12), s13 = sum2(p13);
                s00 += __shfl_xor_sync(0xffffffffu, s00, 1);
                s01 += __shfl_xor_sync(0xffffffffu, s01, 1);
                s02 += __shfl_xor_sync(0xffffffffu, s02, 1);
                s03 += __shfl_xor_sync(0xffffffffu, s03, 1);
                s10 += __shfl_xor_sync(0xffffffffu, s10, 1);
                s11 += __shfl_xor_sync(0xffffffffu, s11, 1);
                s12 += __shfl_xor_sync(0xffffffffu, s12, 1);
                s13 += __shfl_xor_sync(0xffffffffu, s13, 1);
                if (kh == 0) {
                    float* q0 = &g2buf[r0 * GSTRIDE];
                    float* q1 = &g2buf[r1 * GSTRIDE];
                    q0[0] = s00; q0[1] = s01; q0[2] = s02; q0[3] = s03;
                    q1[0] = s10; q1[1] = s11; q1[2] = s12; q1[3] = s13;
                }
            }
            asm volatile("bar.sync 2, 128;" ::: "memory");

            // cell2 (step i-1)
            {
                float gi = g2buf[(cu)      * GSTRIDE + cb] + bias2s[cu];
                float gf = g2buf[(32 + cu) * GSTRIDE + cb] + bias2s[32 + cu];
                float gg = g2buf[(64 + cu) * GSTRIDE + cb] + bias2s[64 + cu];
                float go = g2buf[(96 + cu) * GSTRIDE + cb] + bias2s[96 + cu];
                c2s = sigm(gf) * c2s + sigm(gi) * tanh_fast(gg);
                float h2n = sigm(go) * tanh_fast(c2s);
                if (i < TSEQ) {
                    #pragma unroll
                    for (int r = 0; r < 4; r++)
                        st_cluster_f32(&h2bc[pn][cb * ASTRIDE + pos], r, h2n);
                }
                gh2p[(size_t)(i - 1) * (BATCH * HDIM)] = h2n;
            }
            asm volatile("bar.sync 2, 128;" ::: "memory");
            if (lt == 0 && i < TSEQ) {
                #pragma unroll
                for (int r = 0; r < 4; r++) mbar_arrive_rank(mb2a, r);
            }
        }
    }
}

// ---------------------------------------------------------------------------
__global__ void dots_kernel(const float* __restrict__ w_t)
{
    int gid  = blockIdx.x * blockDim.x + threadIdx.x;
    int gw   = gid >> 5;
    int lane = gid & 31;
    if (gw >= TSEQ * BATCH) return;
    float4 h = *(const float4*)(g_h2 + (size_t)gw * HDIM + lane * 4);
    float4 a = *(const float4*)(w_t + lane * 4);
    float4 o = *(const float4*)(w_t + HDIM + lane * 4);
    float dh   = h.x * a.x + h.y * a.y + h.z * a.z + h.w * a.w;
    float dold = h.x * o.x + h.y * o.y + h.z * o.z + h.w * o.w;
    #pragma unroll
    for (int off = 16; off; off >>= 1) {
        dh   += __shfl_down_sync(0xffffffffu, dh, off);
        dold += __shfl_down_sync(0xffffffffu, dold, off);
    }
    if (lane == 0) { g_dh[gw] = dh; g_dold[gw] = dold; }
}

// ---------------------------------------------------------------------------
__global__ void __launch_bounds__(256, 1)
attn_fc_kernel(const float* __restrict__ fcW, const float* __restrict__ fcb,
               float* __restrict__ out)
{
    extern __shared__ float sm[];
    float* sFcT = sm;                       // [128][132]
    float* sPre = sFcT + 128 * RSTRIDE;     // [128][132]
    float* sE   = sPre + 128 * RSTRIDE;     // [33][128]
    float* sHd  = sE + 33 * 128;            // [128]
    float* sFcb = sHd + 128;                // [128]
    float* sRed = sFcb + 128;               // [256]

    const int t    = blockIdx.x;
    const int tid  = threadIdx.x;
    const int lane = tid & 31;
    const int warp = tid >> 5;

    for (int idx = tid; idx < 128 * 128; idx += 256) {
        int c = idx >> 7, h = idx & 127;
        sFcT[h * RSTRIDE + c] = fcW[idx];
    }
    if (tid < 128) {
        sFcb[tid] = fcb[tid];
        sHd[tid]  = g_dh[t * BATCH + tid];
    }
    __syncthreads();

    const int s_min = (t < 32) ? (32 - t) : 0;
    const int nsc   = (33 - s_min) * 128;
    float lmax = -1e30f;
    for (int n = tid; n < nsc; n += 256) {
        int s = s_min + (n >> 7), b = n & 127;
        int idx = t - 33 + s;
        float sc = sHd[b] + (idx >= 0 ? g_dold[idx * BATCH + b] : 0.f);
        sE[s * 128 + b] = sc;
        lmax = fmaxf(lmax, sc);
    }
    sRed[tid] = lmax; __syncthreads();
    for (int off = 128; off; off >>= 1) {
        if (tid < off) sRed[tid] = fmaxf(sRed[tid], sRed[tid + off]);
        __syncthreads();
    }
    float mx = sRed[0];
    __syncthreads();
    float lsum = 0.f;
    for (int n = tid; n < nsc; n += 256) {
        int s = s_min + (n >> 7), b = n & 127;
        float e = __expf(sE[s * 128 + b] - mx);
        sE[s * 128 + b] = e;
        lsum += e;
    }
    sRed[tid] = lsum; __syncthreads();
    for (int off = 128; off; off >>= 1) {
        if (tid < off) sRed[tid] += sRed[tid + off];
        __syncthreads();
    }
    float inv = __fdividef(1.f, sRed[0]);
    __syncthreads();

    const int s_att = (t < 33) ? (33 - t) : 0;
    for (int b = warp; b < 128; b += 8) {
        float4 acc; acc.x = acc.y = acc.z = acc.w = 0.f;
        for (int s = s_att; s < 33; s++) {
            float w  = sE[s * 128 + b];
            float4 v = *(const float4*)(g_h2 + (size_t)(t - 33 + s) * (BATCH * HDIM)
                                              + (size_t)b * HDIM + lane * 4);
            acc.x += w * v.x; acc.y += w * v.y; acc.z += w * v.z; acc.w += w * v.w;
        }
        float4 hc = *(const float4*)(g_h2 + (size_t)t * (BATCH * HDIM)
                                           + (size_t)b * HDIM + lane * 4);
        float4 pre;
        pre.x = hc.x + inv * acc.x; pre.y = hc.y + inv * acc.y;
        pre.z = hc.z + inv * acc.z; pre.w = hc.w + inv * acc.w;
        *(float4*)(sPre + b * RSTRIDE + lane * 4) = pre;
    }
    __syncthreads();

    const int c0 = lane * 4;
    float4 bias = *(const float4*)(sFcb + c0);
    for (int r = 0; r < 4; r++) {
        int b0 = (warp + 8 * r) * 4;
        u64 A0l = 0, A0h = 0, A1l = 0, A1h = 0, A2l = 0, A2h = 0, A3l = 0, A3h = 0;
        const float4* p0 = (const float4*)(sPre + (size_t)(b0 + 0) * RSTRIDE);
        const float4* p1 = (const float4*)(sPre + (size_t)(b0 + 1) * RSTRIDE);
        const float4* p2 = (const float4*)(sPre + (size_t)(b0 + 2) * RSTRIDE);
        const float4* p3 = (const float4*)(sPre + (size_t)(b0 + 3) * RSTRIDE);
        #pragma unroll
        for (int h4 = 0; h4 < 32; h4++) {
            float4 q0 = p0[h4], q1 = p1[h4], q2 = p2[h4], q3 = p3[h4];
            #pragma unroll
            for (int hh = 0; hh < 4; hh++) {
                ulonglong2 wv = *(const ulonglong2*)(sFcT + (h4 * 4 + hh) * RSTRIDE + c0);
                float f0 = (&q0.x)[hh], f1 = (&q1.x)[hh], f2 = (&q2.x)[hh], f3 = (&q3.x)[hh];
                u64 v0 = pack2(f0, f0), v1 = pack2(f1, f1);
                u64 v2 = pack2(f2, f2), v3 = pack2(f3, f3);
                A0l = ffma2(v0, wv.x, A0l); A0h = ffma2(v0, wv.y, A0h);
                A1l = ffma2(v1, wv.x, A1l); A1h = ffma2(v1, wv.y, A1h);
                A2l = ffma2(v2, wv.x, A2l); A2h = ffma2(v2, wv.y, A2h);
                A3l = ffma2(v3, wv.x, A3l); A3h = ffma2(v3, wv.y, A3h);
            }
        }
        float2 l0 = unpk(A0l), h0 = unpk(A0h), l1 = unpk(A1l), h1 = unpk(A1h);
        float2 l2 = unpk(A2l), h2 = unpk(A2h), l3 = unpk(A3l), h3 = unpk(A3h);
        float4 a0 = make_float4(l0.x + bias.x, l0.y + bias.y, h0.x + bias.z, h0.y + bias.w);
        float4 a1 = make_float4(l1.x + bias.x, l1.y + bias.y, h1.x + bias.z, h1.y + bias.w);
        float4 a2 = make_float4(l2.x + bias.x, l2.y + bias.y, h2.x + bias.z, h2.y + bias.w);
        float4 a3 = make_float4(l3.x + bias.x, l3.y + bias.y, h3.x + bias.z, h3.y + bias.w);
        size_t obase = (size_t)t * 128 + c0;
        *(float4*)(out + (size_t)(b0 + 0) * (TSEQ * 128) + obase) = a0;
        *(float4*)(out + (size_t)(b0 + 1) * (TSEQ * 128) + obase) = a1;
        *(float4*)(out + (size_t)(b0 + 2) * (TSEQ * 128) + obase) = a2;
        *(float4*)(out + (size_t)(b0 + 3) * (TSEQ * 128) + obase) = a3;
    }
}

// ---------------------------------------------------------------------------
extern "C" void kernel_launch(void* const* d_in, const int* in_sizes, int n_in,
                              void* d_out, int out_size)
{
    const float* x    = (const float*)d_in[0];
    const float* Wih1 = (const float*)d_in[1];
    const float* Whh1 = (const float*)d_in[2];
    const float* bih1 = (const float*)d_in[3];
    const float* bhh1 = (const float*)d_in[4];
    const float* Wih2 = (const float*)d_in[5];
    const float* Whh2 = (const float*)d_in[6];
    const float* bih2 = (const float*)d_in[7];
    const float* bhh2 = (const float*)d_in[8];
    const float* w_t  = (const float*)d_in[9];
    const float* fcW  = (const float*)d_in[10];
    const float* fcb  = (const float*)d_in[11];
    float* out = (float*)d_out;

    const int smem1 = 256 * WSTRIDE * (int)sizeof(float);   // 135168
    const int smem3 = (2 * 128 * RSTRIDE + 33 * 128 + 128 + 128 + 256) * (int)sizeof(float);

    cudaFuncSetAttribute(lstm_seq_kernel, cudaFuncAttributeMaxDynamicSharedMemorySize, smem1);
    cudaFuncSetAttribute(attn_fc_kernel,  cudaFuncAttributeMaxDynamicSharedMemorySize, smem3);

    lstm_seq_kernel<<<128, 256, smem1>>>(x, Wih1, Whh1, bih1, bhh1,
                                         Wih2, Whh2, bih2, bhh2);
    dots_kernel<<<(TSEQ * BATCH * 32) / 256, 256>>>(w_t);
    attn_fc_kernel<<<TSEQ, 256, smem3>>>(fcW, fcb, out);
}

// round 13
// speedup vs baseline: 1.1054x; 1.1054x over previous
#include <cuda_runtime.h>
#include <cstdint>

#define HDIM 128
#define TSEQ 512
#define BATCH 128
#define GB 4
#define RSTRIDE 132
#define WSTRIDE 132
#define ASTRIDE 132     // activation row stride; dims 64..127 live at float-offset 68
#define GSTRIDE 9       // gate-buffer row stride -> conflict-free scalar access

typedef unsigned long long u64;

__device__ float g_h2[(size_t)TSEQ * BATCH * HDIM];   // [t][b][h]
__device__ float g_dold[TSEQ * BATCH];
__device__ float g_dh[TSEQ * BATCH];

__device__ __forceinline__ float sigm(float x) {
    return __fdividef(1.f, 1.f + __expf(-x));
}
__device__ __forceinline__ float tanh_fast(float x) {
    x = fminf(fmaxf(x, -15.f), 15.f);
    float e = __expf(2.f * x);
    return __fdividef(e - 1.f, e + 1.f);
}
__device__ __forceinline__ u64 ffma2(u64 a, u64 b, u64 c) {
    u64 d;
    asm("fma.rn.f32x2 %0, %1, %2, %3;" : "=l"(d) : "l"(a), "l"(b), "l"(c));
    return d;
}
__device__ __forceinline__ float sum2(u64 v) {
    float lo, hi;
    asm("mov.b64 {%0, %1}, %2;" : "=f"(lo), "=f"(hi) : "l"(v));
    return lo + hi;
}
__device__ __forceinline__ void st_cluster_f32(float* p, int rank, float v) {
    uint32_t la = (uint32_t)__cvta_generic_to_shared(p);
    uint32_t ra;
    asm volatile("mapa.shared::cluster.u32 %0, %1, %2;" : "=r"(ra) : "r"(la), "r"(rank));
    asm volatile("st.shared::cluster.f32 [%0], %1;" :: "r"(ra), "f"(v) : "memory");
}
__device__ __forceinline__ void mbar_init(uint32_t a, uint32_t cnt) {
    asm volatile("mbarrier.init.shared.b64 [%0], %1;" :: "r"(a), "r"(cnt) : "memory");
}
__device__ __forceinline__ void mbar_arrive_rank(uint32_t local_addr, uint32_t rank) {
    asm volatile(
        "{\n\t.reg .b32 ra;\n\t"
        "mapa.shared::cluster.u32 ra, %0, %1;\n\t"
        "mbarrier.arrive.release.cluster.shared::cluster.b64 _, [ra];\n\t}"
        :: "r"(local_addr), "r"(rank) : "memory");
}
__device__ __forceinline__ void mbar_wait(uint32_t addr, uint32_t parity) {
    asm volatile(
        "{\n\t.reg .pred P;\n"
        "WL_%=:\n\t"
        "mbarrier.try_wait.parity.acquire.cluster.shared::cta.b64 P, [%0], %1, 0x989680;\n\t"
        "@P bra WD_%=;\n\t"
        "bra WL_%=;\n"
        "WD_%=:\n\t}"
        :: "r"(addr), "r"(parity) : "memory");
}
__device__ __forceinline__ void cluster_sync_() {
    asm volatile("barrier.cluster.arrive.aligned;" ::: "memory");
    asm volatile("barrier.cluster.wait.aligned;" ::: "memory");
}

// ---------------------------------------------------------------------------
// Phase 1 (R12, best measured: 1.432 ms): layer-split warp specialization.
//  Group A (tid<128):  layer 1, Whh1 row in REGISTERS.
//  Group B (tid>=128): layer 2, Wih2/Whh2 in SMEM (kh-gap layout).
// No CTA-wide sync in the loop; split DSMEM mbarriers; each SMSP carries one
// A-warp + one B-warp so pipeline stalls cross-cover.
// ---------------------------------------------------------------------------
__global__ void __launch_bounds__(256, 1) __cluster_dims__(4, 1, 1)
lstm_seq_kernel(const float* __restrict__ x,
                const float* __restrict__ Wih1, const float* __restrict__ Whh1,
                const float* __restrict__ bih1, const float* __restrict__ bhh1,
                const float* __restrict__ Wih2, const float* __restrict__ Whh2,
                const float* __restrict__ bih2, const float* __restrict__ bhh2)
{
    extern __shared__ float sW2[];   // [256][WSTRIDE] rows 0-127 Wih2, 128-255 Whh2; kh-gap cols

    __shared__ __align__(16) float h1bc[2][GB * ASTRIDE];
    __shared__ __align__(16) float c1bc[2][GB * ASTRIDE];
    __shared__ __align__(16) float h2bc[2][GB * ASTRIDE];
    __shared__ float g1buf[128 * GSTRIDE];
    __shared__ float g2buf[128 * GSTRIDE];
    __shared__ float bias1s[128], bias2s[128], wih1s[128];
    __shared__ __align__(8) u64 mbar[2];

    const int tid  = threadIdx.x;
    const int rank = blockIdx.x & 3;
    const int bg0  = (blockIdx.x >> 2) * GB;
    const int lt   = tid & 127;

    const int cu   = lt & 31, cb = lt >> 5;
    const int slot = rank * 32 + cu;
    const int pos  = slot + (slot >= 64 ? 4 : 0);   // gap-layout position

    // ---- group A: Whh1 row lt -> registers (64 u64)
    u64 w1[64];
    if (tid < 128) {
        const int gr = (lt >> 5) * 128 + rank * 32 + (lt & 31);
        const float* src = Whh1 + (size_t)gr * 128;
        #pragma unroll
        for (int k = 0; k < 32; k++) {
            ulonglong2 v = ((const ulonglong2*)src)[k];
            w1[2 * k] = v.x; w1[2 * k + 1] = v.y;
        }
    }

    // ---- sW2: both layer-2 matrices, kh-gap column layout
    for (int idx = tid; idx < 256 * 32; idx += 256) {
        int j = idx >> 5, k4 = idx & 31;
        int jr = j & 127;
        int gr = (jr >> 5) * 128 + rank * 32 + (jr & 31);
        const float* src = ((j >> 7) ? Whh2 : Wih2) + (size_t)gr * 128 + k4 * 4;
        int dstc = (k4 < 16) ? (k4 * 4) : (k4 * 4 + 4);
        *(float4*)(sW2 + j * WSTRIDE + dstc) = *(const float4*)src;
    }
    if (tid < 128) {
        int gr = (tid >> 5) * 128 + rank * 32 + (tid & 31);
        bias1s[tid] = bih1[gr] + bhh1[gr];
        bias2s[tid] = bih2[gr] + bhh2[gr];
        wih1s[tid]  = Wih1[gr];
    }
    for (int idx = tid; idx < 2 * GB * ASTRIDE; idx += 256) {
        ((float*)h1bc)[idx] = 0.f;
        ((float*)c1bc)[idx] = 0.f;
        ((float*)h2bc)[idx] = 0.f;
    }
    const uint32_t mb1a = (uint32_t)__cvta_generic_to_shared(&mbar[0]);
    const uint32_t mb2a = (uint32_t)__cvta_generic_to_shared(&mbar[1]);
    if (tid == 0) { mbar_init(mb1a, 4); mbar_init(mb2a, 4); }
    __syncthreads();
    cluster_sync_();   // peers see zeroed buffers + initialized mbarriers

    if (tid < 128) {
        // ============================ GROUP A ============================
        float c1s = 0.f;
        const float* xp = x + (size_t)(bg0 + cb) * TSEQ;
        for (int i = 0; i < TSEQ; i++) {
            const int p  = i & 1;
            const int pn = p ^ 1;
            if (i > 0) mbar_wait(mb1a, (uint32_t)((i - 1) & 1));

            // mv1: reg row (full K) . h1(i-1), 4 batches (gap act layout)
            {
                const ulonglong2* hA = (const ulonglong2*)(&h1bc[p][0 * ASTRIDE]);
                const ulonglong2* hB = (const ulonglong2*)(&h1bc[p][1 * ASTRIDE]);
                const ulonglong2* hC = (const ulonglong2*)(&h1bc[p][2 * ASTRIDE]);
                const ulonglong2* hD = (const ulonglong2*)(&h1bc[p][3 * ASTRIDE]);
                u64 a0 = 0, a1 = 0, a2 = 0, a3 = 0;
                #pragma unroll
                for (int k = 0; k < 32; k++) {
                    int ki = k + (k >= 16 ? 1 : 0);   // skip gap at float 64..67
                    ulonglong2 v0 = hA[ki], v1 = hB[ki], v2 = hC[ki], v3 = hD[ki];
                    u64 wa = w1[2 * k], wb = w1[2 * k + 1];
                    a0 = ffma2(wa, v0.x, a0); a0 = ffma2(wb, v0.y, a0);
                    a1 = ffma2(wa, v1.x, a1); a1 = ffma2(wb, v1.y, a1);
                    a2 = ffma2(wa, v2.x, a2); a2 = ffma2(wb, v2.y, a2);
                    a3 = ffma2(wa, v3.x, a3); a3 = ffma2(wb, v3.y, a3);
                }
                g1buf[lt * GSTRIDE + 0] = sum2(a0);
                g1buf[lt * GSTRIDE + 1] = sum2(a1);
                g1buf[lt * GSTRIDE + 2] = sum2(a2);
                g1buf[lt * GSTRIDE + 3] = sum2(a3);
            }
            asm volatile("bar.sync 1, 128;" ::: "memory");
            if (i > 0) mbar_wait(mb2a, (uint32_t)((i - 1) & 1));  // B's reads of buf pn done

            // cell1 (step i)
            {
                float xv = __ldg(xp + i);
                float gi = g1buf[(cu)      * GSTRIDE + cb] + fmaf(wih1s[cu],      xv, bias1s[cu]);
                float gf = g1buf[(32 + cu) * GSTRIDE + cb] + fmaf(wih1s[32 + cu], xv, bias1s[32 + cu]);
                float gg = g1buf[(64 + cu) * GSTRIDE + cb] + fmaf(wih1s[64 + cu], xv, bias1s[64 + cu]);
                float go = g1buf[(96 + cu) * GSTRIDE + cb] + fmaf(wih1s[96 + cu], xv, bias1s[96 + cu]);
                c1s = sigm(gf) * c1s + sigm(gi) * tanh_fast(gg);
                float h1n = sigm(go) * tanh_fast(c1s);
                #pragma unroll
                for (int r = 0; r < 4; r++) {
                    st_cluster_f32(&h1bc[pn][cb * ASTRIDE + pos], r, h1n);
                    st_cluster_f32(&c1bc[pn][cb * ASTRIDE + pos], r, c1s);
                }
            }
            asm volatile("bar.sync 1, 128;" ::: "memory");
            if (lt == 0) {
                #pragma unroll
                for (int r = 0; r < 4; r++) mbar_arrive_rank(mb1a, r);
            }
        }
    } else {
        // ============================ GROUP B ============================
        const int u  = lt >> 1;
        const int kh = lt & 1;
        const int r0 = 2 * u, r1 = 2 * u + 1;
        float c2s = 0.f;
        float* gh2p = g_h2 + (size_t)(bg0 + cb) * HDIM + slot;

        if (lt == 0) {   // iteration-0 arrive so A's first mb2 wait passes
            #pragma unroll
            for (int r = 0; r < 4; r++) mbar_arrive_rank(mb2a, r);
        }
        for (int i = 1; i <= TSEQ; i++) {
            const int p  = i & 1;
            const int pn = p ^ 1;
            const uint32_t wpar = (uint32_t)((i - 1) & 1);
            mbar_wait(mb1a, wpar);   // c1(i-1) data
            mbar_wait(mb2a, wpar);   // h2(i-2) data + own WAR

            // mv2: gates2(step i-1) rows r0,r1 = Wih2.c1(i-1) + Whh2.h2(i-2), kh half
            {
                const ulonglong2* wi0 = (const ulonglong2*)(sW2 + r0 * WSTRIDE + kh * 68);
                const ulonglong2* wi1 = (const ulonglong2*)(sW2 + r1 * WSTRIDE + kh * 68);
                const ulonglong2* wh0 = (const ulonglong2*)(sW2 + (128 + r0) * WSTRIDE + kh * 68);
                const ulonglong2* wh1 = (const ulonglong2*)(sW2 + (128 + r1) * WSTRIDE + kh * 68);
                const ulonglong2* cA = (const ulonglong2*)(&c1bc[p][0 * ASTRIDE + kh * 68]);
                const ulonglong2* cB = (const ulonglong2*)(&c1bc[p][1 * ASTRIDE + kh * 68]);
                const ulonglong2* cC = (const ulonglong2*)(&c1bc[p][2 * ASTRIDE + kh * 68]);
                const ulonglong2* cD = (const ulonglong2*)(&c1bc[p][3 * ASTRIDE + kh * 68]);
                const ulonglong2* hA = (const ulonglong2*)(&h2bc[p][0 * ASTRIDE + kh * 68]);
                const ulonglong2* hB = (const ulonglong2*)(&h2bc[p][1 * ASTRIDE + kh * 68]);
                const ulonglong2* hC = (const ulonglong2*)(&h2bc[p][2 * ASTRIDE + kh * 68]);
                const ulonglong2* hD = (const ulonglong2*)(&h2bc[p][3 * ASTRIDE + kh * 68]);
                u64 p00 = 0, p01 = 0, p02 = 0, p03 = 0;
                u64 p10 = 0, p11 = 0, p12 = 0, p13 = 0;
                #pragma unroll
                for (int k = 0; k < 16; k++) {
                    ulonglong2 wiA = wi0[k], wiB = wi1[k];
                    ulonglong2 whA = wh0[k], whB = wh1[k];
                    ulonglong2 v0 = cA[k], v1 = cB[k], v2 = cC[k], v3 = cD[k];
                    ulonglong2 u0 = hA[k], u1 = hB[k], u2 = hC[k], u3 = hD[k];
                    p00 = ffma2(wiA.x, v0.x, p00); p00 = ffma2(wiA.y, v0.y, p00);
                    p00 = ffma2(whA.x, u0.x, p00); p00 = ffma2(whA.y, u0.y, p00);
                    p01 = ffma2(wiA.x, v1.x, p01); p01 = ffma2(wiA.y, v1.y, p01);
                    p01 = ffma2(whA.x, u1.x, p01); p01 = ffma2(whA.y, u1.y, p01);
                    p02 = ffma2(wiA.x, v2.x, p02); p02 = ffma2(wiA.y, v2.y, p02);
                    p02 = ffma2(whA.x, u2.x, p02); p02 = ffma2(whA.y, u2.y, p02);
                    p03 = ffma2(wiA.x, v3.x, p03); p03 = ffma2(wiA.y, v3.y, p03);
                    p03 = ffma2(whA.x, u3.x, p03); p03 = ffma2(whA.y, u3.y, p03);
                    p10 = ffma2(wiB.x, v0.x, p10); p10 = ffma2(wiB.y, v0.y, p10);
                    p10 = ffma2(whB.x, u0.x, p10); p10 = ffma2(whB.y, u0.y, p10);
                    p11 = ffma2(wiB.x, v1.x, p11); p11 = ffma2(wiB.y, v1.y, p11);
                    p11 = ffma2(whB.x, u1.x, p11); p11 = ffma2(whB.y, u1.y, p11);
                    p12 = ffma2(wiB.x, v2.x, p12); p12 = ffma2(wiB.y, v2.y, p12);
                    p12 = ffma2(whB.x, u2.x, p12); p12 = ffma2(whB.y, u2.y, p12);
                    p13 = ffma2(wiB.x, v3.x, p13); p13 = ffma2(wiB.y, v3.y, p13);
                    p13 = ffma2(whB.x, u3.x, p13); p13 = ffma2(whB.y, u3.y, p13);
                }
                float s00 = sum2(p00), s01 = sum2(p01), s02 = sum2(p02), s03 = sum2(p03);
                float s10 = sum2(p10), s11 = sum2(p11), s12 = sum2(p12), s13 = sum2(p13);
                s00 += __shfl_xor_sync(0xffffffffu, s00, 1);
                s01 += __shfl_xor_sync(0xffffffffu, s01, 1);
                s02 += __shfl_xor_sync(0xffffffffu, s02, 1);
                s03 += __shfl_xor_sync(0xffffffffu, s03, 1);
                s10 += __shfl_xor_sync(0xffffffffu, s10, 1);
                s11 += __shfl_xor_sync(0xffffffffu, s11, 1);
                s12 += __shfl_xor_sync(0xffffffffu, s12, 1);
                s13 += __shfl_xor_sync(0xffffffffu, s13, 1);
                if (kh == 0) {
                    float* q0 = &g2buf[r0 * GSTRIDE];
                    float* q1 = &g2buf[r1 * GSTRIDE];
                    q0[0] = s00; q0[1] = s01; q0[2] = s02; q0[3] = s03;
                    q1[0] = s10; q1[1] = s11; q1[2] = s12; q1[3] = s13;
                }
            }
            asm volatile("bar.sync 2, 128;" ::: "memory");

            // cell2 (step i-1)
            {
                float gi = g2buf[(cu)      * GSTRIDE + cb] + bias2s[cu];
                float gf = g2buf[(32 + cu) * GSTRIDE + cb] + bias2s[32 + cu];
                float gg = g2buf[(64 + cu) * GSTRIDE + cb] + bias2s[64 + cu];
                float go = g2buf[(96 + cu) * GSTRIDE + cb] + bias2s[96 + cu];
                c2s = sigm(gf) * c2s + sigm(gi) * tanh_fast(gg);
                float h2n = sigm(go) * tanh_fast(c2s);
                if (i < TSEQ) {
                    #pragma unroll
                    for (int r = 0; r < 4; r++)
                        st_cluster_f32(&h2bc[pn][cb * ASTRIDE + pos], r, h2n);
                }
                gh2p[(size_t)(i - 1) * (BATCH * HDIM)] = h2n;
            }
            asm volatile("bar.sync 2, 128;" ::: "memory");
            if (lt == 0 && i < TSEQ) {
                #pragma unroll
                for (int r = 0; r < 4; r++) mbar_arrive_rank(mb2a, r);
            }
        }
    }
}

// ---------------------------------------------------------------------------
__global__ void dots_kernel(const float* __restrict__ w_t)
{
    int gid  = blockIdx.x * blockDim.x + threadIdx.x;
    int gw   = gid >> 5;
    int lane = gid & 31;
    if (gw >= TSEQ * BATCH) return;
    float4 h = *(const float4*)(g_h2 + (size_t)gw * HDIM + lane * 4);
    float4 a = *(const float4*)(w_t + lane * 4);
    float4 o = *(const float4*)(w_t + HDIM + lane * 4);
    float dh   = h.x * a.x + h.y * a.y + h.z * a.z + h.w * a.w;
    float dold = h.x * o.x + h.y * o.y + h.z * o.z + h.w * o.w;
    #pragma unroll
    for (int off = 16; off; off >>= 1) {
        dh   += __shfl_down_sync(0xffffffffu, dh, off);
        dold += __shfl_down_sync(0xffffffffu, dold, off);
    }
    if (lane == 0) { g_dh[gw] = dh; g_dold[gw] = dold; }
}

// ---------------------------------------------------------------------------
// Phase 2b (R11 version, measured ~258us total phase-2): scalar-FMA FC.
// ---------------------------------------------------------------------------
__global__ void __launch_bounds__(256, 1)
attn_fc_kernel(const float* __restrict__ fcW, const float* __restrict__ fcb,
               float* __restrict__ out)
{
    extern __shared__ float sm[];
    float* sFcT = sm;                       // [128][132]
    float* sPre = sFcT + 128 * RSTRIDE;     // [128][132]
    float* sE   = sPre + 128 * RSTRIDE;     // [33][128]
    float* sHd  = sE + 33 * 128;            // [128]
    float* sFcb = sHd + 128;                // [128]
    float* sRed = sFcb + 128;               // [256]

    const int t    = blockIdx.x;
    const int tid  = threadIdx.x;
    const int lane = tid & 31;
    const int warp = tid >> 5;

    for (int idx = tid; idx < 128 * 128; idx += 256) {
        int c = idx >> 7, h = idx & 127;
        sFcT[h * RSTRIDE + c] = fcW[idx];
    }
    if (tid < 128) {
        sFcb[tid] = fcb[tid];
        sHd[tid]  = g_dh[t * BATCH + tid];
    }
    __syncthreads();

    const int s_min = (t < 32) ? (32 - t) : 0;
    const int nsc   = (33 - s_min) * 128;
    float lmax = -1e30f;
    for (int n = tid; n < nsc; n += 256) {
        int s = s_min + (n >> 7), b = n & 127;
        int idx = t - 33 + s;
        float sc = sHd[b] + (idx >= 0 ? g_dold[idx * BATCH + b] : 0.f);
        sE[s * 128 + b] = sc;
        lmax = fmaxf(lmax, sc);
    }
    sRed[tid] = lmax; __syncthreads();
    for (int off = 128; off; off >>= 1) {
        if (tid < off) sRed[tid] = fmaxf(sRed[tid], sRed[tid + off]);
        __syncthreads();
    }
    float mx = sRed[0];
    __syncthreads();
    float lsum = 0.f;
    for (int n = tid; n < nsc; n += 256) {
        int s = s_min + (n >> 7), b = n & 127;
        float e = __expf(sE[s * 128 + b] - mx);
        sE[s * 128 + b] = e;
        lsum += e;
    }
    sRed[tid] = lsum; __syncthreads();
    for (int off = 128; off; off >>= 1) {
        if (tid < off) sRed[tid] += sRed[tid + off];
        __syncthreads();
    }
    float inv = __fdividef(1.f, sRed[0]);
    __syncthreads();

    const int s_att = (t < 33) ? (33 - t) : 0;
    for (int b = warp; b < 128; b += 8) {
        float4 acc; acc.x = acc.y = acc.z = acc.w = 0.f;
        for (int s = s_att; s < 33; s++) {
            float w  = sE[s * 128 + b];
            float4 v = *(const float4*)(g_h2 + (size_t)(t - 33 + s) * (BATCH * HDIM)
                                              + (size_t)b * HDIM + lane * 4);
            acc.x += w * v.x; acc.y += w * v.y; acc.z += w * v.z; acc.w += w * v.w;
        }
        float4 hc = *(const float4*)(g_h2 + (size_t)t * (BATCH * HDIM)
                                           + (size_t)b * HDIM + lane * 4);
        float4 pre;
        pre.x = hc.x + inv * acc.x; pre.y = hc.y + inv * acc.y;
        pre.z = hc.z + inv * acc.z; pre.w = hc.w + inv * acc.w;
        *(float4*)(sPre + b * RSTRIDE + lane * 4) = pre;
    }
    __syncthreads();

    const int c0 = lane * 4;
    float4 bias = *(const float4*)(sFcb + c0);
    for (int r = 0; r < 4; r++) {
        int b0 = (warp + 8 * r) * 4;
        float4 a0, a1, a2, a3;
        a0.x=a0.y=a0.z=a0.w=0.f; a1=a0; a2=a0; a3=a0;
        const float4* p0 = (const float4*)(sPre + (size_t)(b0 + 0) * RSTRIDE);
        const float4* p1 = (const float4*)(sPre + (size_t)(b0 + 1) * RSTRIDE);
        const float4* p2 = (const float4*)(sPre + (size_t)(b0 + 2) * RSTRIDE);
        const float4* p3 = (const float4*)(sPre + (size_t)(b0 + 3) * RSTRIDE);
        #pragma unroll
        for (int h4 = 0; h4 < 32; h4++) {
            float4 q0 = p0[h4], q1 = p1[h4], q2 = p2[h4], q3 = p3[h4];
            #pragma unroll
            for (int hh = 0; hh < 4; hh++) {
                float4 w = *(const float4*)(sFcT + (h4 * 4 + hh) * RSTRIDE + c0);
                float v0 = (&q0.x)[hh], v1 = (&q1.x)[hh], v2 = (&q2.x)[hh], v3 = (&q3.x)[hh];
                a0.x += v0 * w.x; a0.y += v0 * w.y; a0.z += v0 * w.z; a0.w += v0 * w.w;
                a1.x += v1 * w.x; a1.y += v1 * w.y; a1.z += v1 * w.z; a1.w += v1 * w.w;
                a2.x += v2 * w.x; a2.y += v2 * w.y; a2.z += v2 * w.z; a2.w += v2 * w.w;
                a3.x += v3 * w.x; a3.y += v3 * w.y; a3.z += v3 * w.z; a3.w += v3 * w.w;
            }
        }
        a0.x += bias.x; a0.y += bias.y; a0.z += bias.z; a0.w += bias.w;
        a1.x += bias.x; a1.y += bias.y; a1.z += bias.z; a1.w += bias.w;
        a2.x += bias.x; a2.y += bias.y; a2.z += bias.z; a2.w += bias.w;
        a3.x += bias.x; a3.y += bias.y; a3.z += bias.z; a3.w += bias.w;
        size_t obase = (size_t)t * 128 + c0;
        *(float4*)(out + (size_t)(b0 + 0) * (TSEQ * 128) + obase) = a0;
        *(float4*)(out + (size_t)(b0 + 1) * (TSEQ * 128) + obase) = a1;
        *(float4*)(out + (size_t)(b0 + 2) * (TSEQ * 128) + obase) = a2;
        *(float4*)(out + (size_t)(b0 + 3) * (TSEQ * 128) + obase) = a3;
    }
}

// ---------------------------------------------------------------------------
extern "C" void kernel_launch(void* const* d_in, const int* in_sizes, int n_in,
                              void* d_out, int out_size)
{
    const float* x    = (const float*)d_in[0];
    const float* Wih1 = (const float*)d_in[1];
    const float* Whh1 = (const float*)d_in[2];
    const float* bih1 = (const float*)d_in[3];
    const float* bhh1 = (const float*)d_in[4];
    const float* Wih2 = (const float*)d_in[5];
    const float* Whh2 = (const float*)d_in[6];
    const float* bih2 = (const float*)d_in[7];
    const float* bhh2 = (const float*)d_in[8];
    const float* w_t  = (const float*)d_in[9];
    const float* fcW  = (const float*)d_in[10];
    const float* fcb  = (const float*)d_in[11];
    float* out = (float*)d_out;

    const int smem1 = 256 * WSTRIDE * (int)sizeof(float);   // 135168
    const int smem3 = (2 * 128 * RSTRIDE + 33 * 128 + 128 + 128 + 256) * (int)sizeof(float);

    cudaFuncSetAttribute(lstm_seq_kernel, cudaFuncAttributeMaxDynamicSharedMemorySize, smem1);
    cudaFuncSetAttribute(attn_fc_kernel,  cudaFuncAttributeMaxDynamicSharedMemorySize, smem3);

    lstm_seq_kernel<<<128, 256, smem1>>>(x, Wih1, Whh1, bih1, bhh1,
                                         Wih2, Whh2, bih2, bhh2);
    dots_kernel<<<(TSEQ * BATCH * 32) / 256, 256>>>(w_t);
    attn_fc_kernel<<<TSEQ, 256, smem3>>>(fcW, fcb, out);
}